// round 1
// baseline (speedup 1.0000x reference)
#include <cuda_runtime.h>
#include <math.h>

#define TNUM 4096
#define CH 128
#define NE 16
#define KB 32
#define VSZ 50257

// scratch (static device arrays — no allocation)
__device__ float g_x [TNUM*CH];
__device__ float g_q [TNUM*CH];
__device__ float g_rw[TNUM*NE];
__device__ float g_ao[TNUM*CH];
__device__ float g_xf[TNUM*CH];

// ---------------- packed f32x2 helpers ----------------
__device__ __forceinline__ unsigned long long pk2(float lo, float hi) {
    unsigned long long r;
    asm("mov.b64 %0, {%1, %2};" : "=l"(r) : "f"(lo), "f"(hi));
    return r;
}
__device__ __forceinline__ void upk2(unsigned long long v, float& lo, float& hi) {
    asm("mov.b64 {%0, %1}, %2;" : "=f"(lo), "=f"(hi) : "l"(v));
}
__device__ __forceinline__ void fma2(unsigned long long& d, unsigned long long a, unsigned long long b) {
    asm("fma.rn.f32x2 %0, %1, %2, %3;" : "=l"(d) : "l"(a), "l"(b), "l"(d));
}

// ---------------- block reduce over 128 threads ----------------
__device__ __forceinline__ float blockReduce128(float v, float* sred, int tid) {
    #pragma unroll
    for (int o = 16; o; o >>= 1) v += __shfl_down_sync(0xffffffffu, v, o);
    if ((tid & 31) == 0) sred[tid >> 5] = v;
    __syncthreads();
    return sred[0] + sred[1] + sred[2] + sred[3];
}

// ==================== K1: embed + LN1 + routing + q ====================
__global__ __launch_bounds__(128) void k1(const int* __restrict__ ids,
        const float* __restrict__ emb, const float* __restrict__ router,
        const float* __restrict__ Wq, const float* __restrict__ g1,
        const float* __restrict__ b1, float* __restrict__ gate_out)
{
    int t = blockIdx.x, tid = threadIdx.x;
    __shared__ float sx[CH];
    __shared__ float sred[4];
    __shared__ float sgl[NE];

    int id = ids[t];
    float xv = __ldg(&emb[(long long)id * CH + tid]);
    g_x[t*CH + tid] = xv;

    float mu = blockReduce128(xv, sred, tid) * (1.f/CH);
    __syncthreads();
    float d  = xv - mu;
    float var = blockReduce128(d*d, sred, tid) * (1.f/CH);
    float xln = d * rsqrtf(var + 1e-5f) * g1[tid] + b1[tid];
    sx[tid] = xln;
    __syncthreads();

    // gate logits: 16 experts x 8 threads
    int e = tid >> 3, l = tid & 7;
    float gl = 0.f;
    #pragma unroll 4
    for (int k = l; k < CH; k += 8) gl += sx[k] * __ldg(&router[e*CH + k]);
    #pragma unroll
    for (int o = 4; o; o >>= 1) gl += __shfl_xor_sync(0xffffffffu, gl, o, 8);
    if (l == 0) sgl[e] = gl;
    __syncthreads();

    if (tid < NE) gate_out[(long long)t*NE + tid] = sgl[tid];

    float mx = -1e30f;
    #pragma unroll
    for (int i = 0; i < NE; i++) mx = fmaxf(mx, sgl[i]);
    float ss = 0.f;
    #pragma unroll
    for (int i = 0; i < NE; i++) ss += __expf(sgl[i] - mx);
    if (tid < NE) g_rw[t*NE + tid] = __expf(sgl[tid] - mx) / ss;

    // q[d] = dot(xln, Wq[d,:])
    float acc = 0.f;
    const float4* wr = (const float4*)(Wq + tid*CH);
    const float4* xr = (const float4*)sx;
    #pragma unroll 8
    for (int k = 0; k < 32; k++) {
        float4 w = __ldg(&wr[k]);
        float4 x4 = xr[k];
        acc += w.x*x4.x + w.y*x4.y + w.z*x4.z + w.w*x4.w;
    }
    g_q[t*CH + tid] = acc;
}

// ==================== K2: expert attention ====================
#define TB 32
#define QSTR 132
__global__ __launch_bounds__(256) void k2(const float* __restrict__ kexp,
        const float* __restrict__ vexp, const float* __restrict__ skv,
        const float* __restrict__ svv, const float* __restrict__ kvg)
{
    __shared__ float sQ[TB*QSTR];
    __shared__ float sT[KB*QSTR];
    __shared__ float sS[TB][KB+1];
    __shared__ float sRW[TB*NE];

    int t0 = blockIdx.x * TB;
    int tid = threadIdx.x;
    float g = 1.f / (1.f + __expf(-kvg[0]));

    for (int i = tid; i < TB*CH; i += 256) {
        int tt = i >> 7, cc = i & 127;
        sQ[tt*QSTR + cc] = g_q[(t0+tt)*CH + cc];
    }
    for (int i = tid; i < TB*NE; i += 256) sRW[i] = g_rw[t0*NE + i];

    int t = tid >> 3, kg = tid & 7;
    float sdyn[4] = {0,0,0,0}, sstat[4];

    // ---- scores: dynamic experts ----
    for (int e = 0; e < NE; e++) {
        __syncthreads();
        for (int i = tid; i < KB*CH; i += 256) {
            int kk = i >> 7, cc = i & 127;
            sT[kk*QSTR + cc] = __ldg(&kexp[e*KB*CH + i]);
        }
        __syncthreads();
        float rwv = sRW[t*NE + e];
        float dj[4] = {0,0,0,0};
        const float4* qp = (const float4*)(sQ + t*QSTR);
        #pragma unroll 4
        for (int c4 = 0; c4 < 32; c4++) {
            float4 qv = qp[c4];
            #pragma unroll
            for (int j = 0; j < 4; j++) {
                int k = kg + 8*j;
                float4 kv = *(const float4*)(sT + k*QSTR + 4*c4);
                dj[j] += qv.x*kv.x + qv.y*kv.y + qv.z*kv.z + qv.w*kv.w;
            }
        }
        #pragma unroll
        for (int j = 0; j < 4; j++) sdyn[j] += rwv * dj[j];
    }
    // ---- scores: static K ----
    __syncthreads();
    for (int i = tid; i < KB*CH; i += 256) {
        int kk = i >> 7, cc = i & 127;
        sT[kk*QSTR + cc] = __ldg(&skv[i]);
    }
    __syncthreads();
    {
        float dj[4] = {0,0,0,0};
        const float4* qp = (const float4*)(sQ + t*QSTR);
        #pragma unroll 4
        for (int c4 = 0; c4 < 32; c4++) {
            float4 qv = qp[c4];
            #pragma unroll
            for (int j = 0; j < 4; j++) {
                int k = kg + 8*j;
                float4 kv = *(const float4*)(sT + k*QSTR + 4*c4);
                dj[j] += qv.x*kv.x + qv.y*kv.y + qv.z*kv.z + qv.w*kv.w;
            }
        }
        #pragma unroll
        for (int j = 0; j < 4; j++) sstat[j] = dj[j];
    }
    const float scale = 0.08838834764831845f; // 1/sqrt(128)
    #pragma unroll
    for (int j = 0; j < 4; j++)
        sS[t][kg + 8*j] = (g*sdyn[j] + (1.f-g)*sstat[j]) * scale;
    __syncthreads();

    // ---- softmax over 32 keys, one thread per token ----
    if (tid < TB) {
        float mx = -1e30f;
        #pragma unroll
        for (int k = 0; k < KB; k++) mx = fmaxf(mx, sS[tid][k]);
        float ssum = 0.f;
        #pragma unroll
        for (int k = 0; k < KB; k++) { float ev = __expf(sS[tid][k] - mx); sS[tid][k] = ev; ssum += ev; }
        float inv = 1.f / ssum;
        #pragma unroll
        for (int k = 0; k < KB; k++) sS[tid][k] *= inv;
    }

    // ---- V mix ----
    float acc[16];
    #pragma unroll
    for (int i = 0; i < 16; i++) acc[i] = 0.f;

    for (int e = 0; e < NE; e++) {
        __syncthreads();
        for (int i = tid; i < KB*CH; i += 256) {
            int kk = i >> 7, cc = i & 127;
            sT[kk*QSTR + cc] = __ldg(&vexp[e*KB*CH + i]);
        }
        __syncthreads();
        float we = g * sRW[t*NE + e];
        #pragma unroll 4
        for (int k = 0; k < KB; k++) {
            float w = we * sS[t][k];
            #pragma unroll
            for (int j = 0; j < 4; j++) {
                float4 vv = *(const float4*)(sT + k*QSTR + 4*(kg + 8*j));
                acc[j*4+0] += w*vv.x; acc[j*4+1] += w*vv.y;
                acc[j*4+2] += w*vv.z; acc[j*4+3] += w*vv.w;
            }
        }
    }
    __syncthreads();
    for (int i = tid; i < KB*CH; i += 256) {
        int kk = i >> 7, cc = i & 127;
        sT[kk*QSTR + cc] = __ldg(&svv[i]);
    }
    __syncthreads();
    {
        float we = 1.f - g;
        #pragma unroll 4
        for (int k = 0; k < KB; k++) {
            float w = we * sS[t][k];
            #pragma unroll
            for (int j = 0; j < 4; j++) {
                float4 vv = *(const float4*)(sT + k*QSTR + 4*(kg + 8*j));
                acc[j*4+0] += w*vv.x; acc[j*4+1] += w*vv.y;
                acc[j*4+2] += w*vv.z; acc[j*4+3] += w*vv.w;
            }
        }
    }
    #pragma unroll
    for (int j = 0; j < 4; j++) {
        float4 o;
        o.x = acc[j*4+0]; o.y = acc[j*4+1]; o.z = acc[j*4+2]; o.w = acc[j*4+3];
        *(float4*)&g_ao[(t0+t)*CH + 4*(kg + 8*j)] = o;
    }
}

// ==================== K3: Wo + residual + LN2 + MLP + residual ====================
__global__ __launch_bounds__(128) void k3(const float* __restrict__ Wo,
        const float* __restrict__ Wm, const float* __restrict__ bm,
        const float* __restrict__ g2, const float* __restrict__ b2)
{
    int t = blockIdx.x, tid = threadIdx.x;
    __shared__ float sa[CH];
    __shared__ float sred[4];

    sa[tid] = g_ao[t*CH + tid];
    __syncthreads();

    float o = 0.f;
    {
        const float4* wr = (const float4*)(Wo + tid*CH);
        const float4* ar = (const float4*)sa;
        #pragma unroll 8
        for (int k = 0; k < 32; k++) {
            float4 w = __ldg(&wr[k]);
            float4 a4 = ar[k];
            o += w.x*a4.x + w.y*a4.y + w.z*a4.z + w.w*a4.w;
        }
    }
    float x2 = g_x[t*CH + tid] + o;

    __syncthreads();
    float mu = blockReduce128(x2, sred, tid) * (1.f/CH);
    __syncthreads();
    float d = x2 - mu;
    float var = blockReduce128(d*d, sred, tid) * (1.f/CH);
    float xln = d * rsqrtf(var + 1e-5f) * g2[tid] + b2[tid];
    __syncthreads();
    sa[tid] = xln;
    __syncthreads();

    float m = __ldg(&bm[tid]);
    {
        const float4* wr = (const float4*)(Wm + tid*CH);
        const float4* ar = (const float4*)sa;
        #pragma unroll 8
        for (int k = 0; k < 32; k++) {
            float4 w = __ldg(&wr[k]);
            float4 a4 = ar[k];
            m += w.x*a4.x + w.y*a4.y + w.z*a4.z + w.w*a4.w;
        }
    }
    g_xf[t*CH + tid] = x2 + m;
}

// ==================== K4: LM head GEMM (f32x2 packed FMA) ====================
#define MT 128
#define NT 128
#define KC 32
#define AST 33
__global__ __launch_bounds__(256) void k4(const float* __restrict__ Wlm,
                                          float* __restrict__ out)
{
    __shared__ float sA[MT*AST]; // [m][k], stride 33
    __shared__ float sB[NT*AST]; // [n][k], stride 33

    int m0 = blockIdx.y * MT, n0 = blockIdx.x * NT;
    int tid = threadIdx.x;
    int tx = tid & 15, ty = tid >> 4;

    unsigned long long acc[8][4];
    #pragma unroll
    for (int i = 0; i < 8; i++)
        #pragma unroll
        for (int j = 0; j < 4; j++) acc[i][j] = 0ULL;

    for (int kc = 0; kc < CH/KC; kc++) {
        int k0 = kc * KC;
        __syncthreads();
        #pragma unroll
        for (int i = 0; i < 4; i++) {
            int idx = tid + i*256;
            int m = idx >> 3, q = idx & 7;
            float4 v = *(const float4*)&g_xf[(m0+m)*CH + k0 + q*4];
            float* dst = &sA[m*AST + q*4];
            dst[0] = v.x; dst[1] = v.y; dst[2] = v.z; dst[3] = v.w;
        }
        #pragma unroll
        for (int i = 0; i < 4; i++) {
            int idx = tid + i*256;
            int n = idx >> 3, q = idx & 7;
            float4 v = make_float4(0.f, 0.f, 0.f, 0.f);
            if (n0 + n < VSZ)
                v = *(const float4*)&Wlm[(long long)(n0+n)*CH + k0 + q*4];
            float* dst = &sB[n*AST + q*4];
            dst[0] = v.x; dst[1] = v.y; dst[2] = v.z; dst[3] = v.w;
        }
        __syncthreads();

        #pragma unroll
        for (int kk = 0; kk < KC; kk++) {
            float a[8];
            unsigned long long b2[4];
            #pragma unroll
            for (int i = 0; i < 8; i++) a[i] = sA[(ty*8 + i)*AST + kk];
            #pragma unroll
            for (int j = 0; j < 4; j++) {
                float blo = sB[(tx*2 + 32*j    )*AST + kk];
                float bhi = sB[(tx*2 + 32*j + 1)*AST + kk];
                b2[j] = pk2(blo, bhi);
            }
            #pragma unroll
            for (int i = 0; i < 8; i++) {
                unsigned long long a2 = pk2(a[i], a[i]);
                #pragma unroll
                for (int j = 0; j < 4; j++) fma2(acc[i][j], a2, b2[j]);
            }
        }
    }

    #pragma unroll
    for (int i = 0; i < 8; i++) {
        long long m = m0 + ty*8 + i;
        float* row = out + (size_t)m * VSZ;
        #pragma unroll
        for (int j = 0; j < 4; j++) {
            int n = n0 + tx*2 + 32*j;
            float lo, hi;
            upk2(acc[i][j], lo, hi);
            if (n     < VSZ) row[n]   = lo;
            if (n + 1 < VSZ) row[n+1] = hi;
        }
    }
}

// ==================== launch ====================
extern "C" void kernel_launch(void* const* d_in, const int* in_sizes, int n_in,
                              void* d_out, int out_size)
{
    const int*   ids    = (const int*)  d_in[0];
    const float* emb    = (const float*)d_in[1];
    const float* router = (const float*)d_in[2];
    const float* kexp   = (const float*)d_in[3];
    const float* vexp   = (const float*)d_in[4];
    const float* skv    = (const float*)d_in[5];
    const float* svv    = (const float*)d_in[6];
    const float* kvg    = (const float*)d_in[7];
    const float* Wq     = (const float*)d_in[8];
    const float* Wo     = (const float*)d_in[9];
    const float* Wm     = (const float*)d_in[10];
    const float* bm     = (const float*)d_in[11];
    const float* g1     = (const float*)d_in[12];
    const float* b1     = (const float*)d_in[13];
    const float* g2     = (const float*)d_in[14];
    const float* b2     = (const float*)d_in[15];
    const float* Wlm    = (const float*)d_in[16];

    float* out = (float*)d_out;
    // outputs concatenated in return order: logits [4096*50257], gate_logits [4096*16]
    float* gate_out = out + ((size_t)out_size - (size_t)TNUM * NE);

    k1<<<TNUM, 128>>>(ids, emb, router, Wq, g1, b1, gate_out);
    k2<<<TNUM/TB, 256>>>(kexp, vexp, skv, svv, kvg);
    k3<<<TNUM, 128>>>(Wo, Wm, bm, g2, b2);
    dim3 g4((VSZ + NT - 1)/NT, TNUM/MT);
    k4<<<g4, 256>>>(Wlm, out);
}

// round 4
// speedup vs baseline: 1.0101x; 1.0101x over previous
#include <cuda_runtime.h>
#include <math.h>
#include <stdint.h>

#define TNUM 4096
#define CH 128
#define NE 16
#define KB 32
#define VSZ 50257
#define NTILES 393   // ceil(50257/128)

// scratch (static device arrays — no allocation)
__device__ float g_x [TNUM*CH];
__device__ float g_q [TNUM*CH];
__device__ float g_rw[TNUM*NE];
__device__ float g_ao[TNUM*CH];
__device__ float g_xf[TNUM*CH];

// ---------------- block reduce over 128 threads ----------------
__device__ __forceinline__ float blockReduce128(float v, float* sred, int tid) {
    #pragma unroll
    for (int o = 16; o; o >>= 1) v += __shfl_down_sync(0xffffffffu, v, o);
    if ((tid & 31) == 0) sred[tid >> 5] = v;
    __syncthreads();
    return sred[0] + sred[1] + sred[2] + sred[3];
}

// ==================== K1: embed + LN1 + routing + q ====================
__global__ __launch_bounds__(128) void k1(const int* __restrict__ ids,
        const float* __restrict__ emb, const float* __restrict__ router,
        const float* __restrict__ Wq, const float* __restrict__ g1,
        const float* __restrict__ b1, float* __restrict__ gate_out)
{
    int t = blockIdx.x, tid = threadIdx.x;
    __shared__ float sx[CH];
    __shared__ float sred[4];
    __shared__ float sgl[NE];

    int id = ids[t];
    float xv = __ldg(&emb[(long long)id * CH + tid]);
    g_x[t*CH + tid] = xv;

    float mu = blockReduce128(xv, sred, tid) * (1.f/CH);
    __syncthreads();
    float d  = xv - mu;
    float var = blockReduce128(d*d, sred, tid) * (1.f/CH);
    float xln = d * rsqrtf(var + 1e-5f) * g1[tid] + b1[tid];
    sx[tid] = xln;
    __syncthreads();

    int e = tid >> 3, l = tid & 7;
    float gl = 0.f;
    #pragma unroll 4
    for (int k = l; k < CH; k += 8) gl += sx[k] * __ldg(&router[e*CH + k]);
    #pragma unroll
    for (int o = 4; o; o >>= 1) gl += __shfl_xor_sync(0xffffffffu, gl, o, 8);
    if (l == 0) sgl[e] = gl;
    __syncthreads();

    if (tid < NE) gate_out[(long long)t*NE + tid] = sgl[tid];

    float mx = -1e30f;
    #pragma unroll
    for (int i = 0; i < NE; i++) mx = fmaxf(mx, sgl[i]);
    float ss = 0.f;
    #pragma unroll
    for (int i = 0; i < NE; i++) ss += __expf(sgl[i] - mx);
    if (tid < NE) g_rw[t*NE + tid] = __expf(sgl[tid] - mx) / ss;

    float acc = 0.f;
    const float4* wr = (const float4*)(Wq + tid*CH);
    const float4* xr = (const float4*)sx;
    #pragma unroll 8
    for (int k = 0; k < 32; k++) {
        float4 w = __ldg(&wr[k]);
        float4 x4 = xr[k];
        acc += w.x*x4.x + w.y*x4.y + w.z*x4.z + w.w*x4.w;
    }
    g_q[t*CH + tid] = acc;
}

// ==================== K2: expert attention ====================
#define TB 32
#define QSTR 132
__global__ __launch_bounds__(256) void k2(const float* __restrict__ kexp,
        const float* __restrict__ vexp, const float* __restrict__ skv,
        const float* __restrict__ svv, const float* __restrict__ kvg)
{
    __shared__ float sQ[TB*QSTR];
    __shared__ float sT[KB*QSTR];
    __shared__ float sS[TB][KB+1];
    __shared__ float sRW[TB*NE];

    int t0 = blockIdx.x * TB;
    int tid = threadIdx.x;
    float g = 1.f / (1.f + __expf(-kvg[0]));

    for (int i = tid; i < TB*CH; i += 256) {
        int tt = i >> 7, cc = i & 127;
        sQ[tt*QSTR + cc] = g_q[(t0+tt)*CH + cc];
    }
    for (int i = tid; i < TB*NE; i += 256) sRW[i] = g_rw[t0*NE + i];

    int t = tid >> 3, kg = tid & 7;
    float sdyn[4] = {0,0,0,0}, sstat[4];

    for (int e = 0; e < NE; e++) {
        __syncthreads();
        for (int i = tid; i < KB*CH; i += 256) {
            int kk = i >> 7, cc = i & 127;
            sT[kk*QSTR + cc] = __ldg(&kexp[e*KB*CH + i]);
        }
        __syncthreads();
        float rwv = sRW[t*NE + e];
        float dj[4] = {0,0,0,0};
        const float4* qp = (const float4*)(sQ + t*QSTR);
        #pragma unroll 4
        for (int c4 = 0; c4 < 32; c4++) {
            float4 qv = qp[c4];
            #pragma unroll
            for (int j = 0; j < 4; j++) {
                int k = kg + 8*j;
                float4 kv = *(const float4*)(sT + k*QSTR + 4*c4);
                dj[j] += qv.x*kv.x + qv.y*kv.y + qv.z*kv.z + qv.w*kv.w;
            }
        }
        #pragma unroll
        for (int j = 0; j < 4; j++) sdyn[j] += rwv * dj[j];
    }
    __syncthreads();
    for (int i = tid; i < KB*CH; i += 256) {
        int kk = i >> 7, cc = i & 127;
        sT[kk*QSTR + cc] = __ldg(&skv[i]);
    }
    __syncthreads();
    {
        float dj[4] = {0,0,0,0};
        const float4* qp = (const float4*)(sQ + t*QSTR);
        #pragma unroll 4
        for (int c4 = 0; c4 < 32; c4++) {
            float4 qv = qp[c4];
            #pragma unroll
            for (int j = 0; j < 4; j++) {
                int k = kg + 8*j;
                float4 kv = *(const float4*)(sT + k*QSTR + 4*c4);
                dj[j] += qv.x*kv.x + qv.y*kv.y + qv.z*kv.z + qv.w*kv.w;
            }
        }
        #pragma unroll
        for (int j = 0; j < 4; j++) sstat[j] = dj[j];
    }
    const float scale = 0.08838834764831845f;
    #pragma unroll
    for (int j = 0; j < 4; j++)
        sS[t][kg + 8*j] = (g*sdyn[j] + (1.f-g)*sstat[j]) * scale;
    __syncthreads();

    if (tid < TB) {
        float mx = -1e30f;
        #pragma unroll
        for (int k = 0; k < KB; k++) mx = fmaxf(mx, sS[tid][k]);
        float ssum = 0.f;
        #pragma unroll
        for (int k = 0; k < KB; k++) { float ev = __expf(sS[tid][k] - mx); sS[tid][k] = ev; ssum += ev; }
        float inv = 1.f / ssum;
        #pragma unroll
        for (int k = 0; k < KB; k++) sS[tid][k] *= inv;
    }

    float acc[16];
    #pragma unroll
    for (int i = 0; i < 16; i++) acc[i] = 0.f;

    for (int e = 0; e < NE; e++) {
        __syncthreads();
        for (int i = tid; i < KB*CH; i += 256) {
            int kk = i >> 7, cc = i & 127;
            sT[kk*QSTR + cc] = __ldg(&vexp[e*KB*CH + i]);
        }
        __syncthreads();
        float we = g * sRW[t*NE + e];
        #pragma unroll 4
        for (int k = 0; k < KB; k++) {
            float w = we * sS[t][k];
            #pragma unroll
            for (int j = 0; j < 4; j++) {
                float4 vv = *(const float4*)(sT + k*QSTR + 4*(kg + 8*j));
                acc[j*4+0] += w*vv.x; acc[j*4+1] += w*vv.y;
                acc[j*4+2] += w*vv.z; acc[j*4+3] += w*vv.w;
            }
        }
    }
    __syncthreads();
    for (int i = tid; i < KB*CH; i += 256) {
        int kk = i >> 7, cc = i & 127;
        sT[kk*QSTR + cc] = __ldg(&svv[i]);
    }
    __syncthreads();
    {
        float we = 1.f - g;
        #pragma unroll 4
        for (int k = 0; k < KB; k++) {
            float w = we * sS[t][k];
            #pragma unroll
            for (int j = 0; j < 4; j++) {
                float4 vv = *(const float4*)(sT + k*QSTR + 4*(kg + 8*j));
                acc[j*4+0] += w*vv.x; acc[j*4+1] += w*vv.y;
                acc[j*4+2] += w*vv.z; acc[j*4+3] += w*vv.w;
            }
        }
    }
    #pragma unroll
    for (int j = 0; j < 4; j++) {
        float4 o;
        o.x = acc[j*4+0]; o.y = acc[j*4+1]; o.z = acc[j*4+2]; o.w = acc[j*4+3];
        *(float4*)&g_ao[(t0+t)*CH + 4*(kg + 8*j)] = o;
    }
}

// ==================== K3: Wo + residual + LN2 + MLP + residual ====================
__global__ __launch_bounds__(128) void k3(const float* __restrict__ Wo,
        const float* __restrict__ Wm, const float* __restrict__ bm,
        const float* __restrict__ g2, const float* __restrict__ b2)
{
    int t = blockIdx.x, tid = threadIdx.x;
    __shared__ float sa[CH];
    __shared__ float sred[4];

    sa[tid] = g_ao[t*CH + tid];
    __syncthreads();

    float o = 0.f;
    {
        const float4* wr = (const float4*)(Wo + tid*CH);
        const float4* ar = (const float4*)sa;
        #pragma unroll 8
        for (int k = 0; k < 32; k++) {
            float4 w = __ldg(&wr[k]);
            float4 a4 = ar[k];
            o += w.x*a4.x + w.y*a4.y + w.z*a4.z + w.w*a4.w;
        }
    }
    float x2 = g_x[t*CH + tid] + o;

    __syncthreads();
    float mu = blockReduce128(x2, sred, tid) * (1.f/CH);
    __syncthreads();
    float d = x2 - mu;
    float var = blockReduce128(d*d, sred, tid) * (1.f/CH);
    float xln = d * rsqrtf(var + 1e-5f) * g2[tid] + b2[tid];
    __syncthreads();
    sa[tid] = xln;
    __syncthreads();

    float m = __ldg(&bm[tid]);
    {
        const float4* wr = (const float4*)(Wm + tid*CH);
        const float4* ar = (const float4*)sa;
        #pragma unroll 8
        for (int k = 0; k < 32; k++) {
            float4 w = __ldg(&wr[k]);
            float4 a4 = ar[k];
            m += w.x*a4.x + w.y*a4.y + w.z*a4.z + w.w*a4.w;
        }
    }
    g_xf[t*CH + tid] = x2 + m;
}

// ==================== K4: LM head GEMM ====================
// D[4096,50257] = Xf[4096,128] @ Wlm[50257,128]^T  (both K-major)

// Feature gate: tcgen05 only exists on the arch-specific (103a) target.
#if defined(__CUDA_ARCH__) && (__CUDA_ARCH__ == 1030) && defined(__CUDA_ARCH_FEAT_SM103_ALL)
#define HAS_TCGEN05 1
#else
#define HAS_TCGEN05 0
#endif

__device__ __forceinline__ uint32_t s2u(const void* p) {
    uint32_t a;
    asm("{ .reg .u64 t; cvta.to.shared.u64 t, %1; cvt.u32.u64 %0, t; }" : "=r"(a) : "l"(p));
    return a;
}

#define SMA 0
#define SMB0 65536
#define SMB1 131072
#define K4_SMEM 196608

#if HAS_TCGEN05

__device__ __forceinline__ uint32_t f2tf(float f) {
    uint32_t r; asm("cvt.rna.tf32.f32 %0, %1;" : "=r"(r) : "f"(f)); return r;
}
__device__ __forceinline__ bool elect1() {
    uint32_t p;
    asm volatile("{ .reg .pred p; elect.sync _|p, 0xFFFFFFFF; selp.b32 %0, 1, 0, p; }" : "=r"(p));
    return p != 0;
}
__device__ __forceinline__ void mbar_init(uint32_t a, uint32_t cnt) {
    asm volatile("mbarrier.init.shared.b64 [%0], %1;" :: "r"(a), "r"(cnt) : "memory");
}
__device__ __forceinline__ void mbar_wait(uint32_t a, uint32_t ph) {
    asm volatile(
        "{\n\t.reg .pred P;\n"
        "W_%=:\n\t"
        "mbarrier.try_wait.parity.acquire.cta.shared::cta.b64 P, [%0], %1, 0x989680;\n\t"
        "@P bra D_%=;\n\t"
        "bra W_%=;\n"
        "D_%=:\n\t}"
        :: "r"(a), "r"(ph) : "memory");
}
__device__ __forceinline__ void sts128(uint32_t a, uint32_t r0, uint32_t r1, uint32_t r2, uint32_t r3) {
    asm volatile("st.shared.v4.b32 [%0], {%1, %2, %3, %4};" :: "r"(a), "r"(r0), "r"(r1), "r"(r2), "r"(r3) : "memory");
}
__device__ __forceinline__ void mma_tf32(uint32_t d, uint64_t ad, uint64_t bd, uint32_t idesc, bool accum) {
    uint32_t en = accum ? 1u : 0u;
    asm volatile(
        "{\n\t.reg .pred p;\n\t"
        "setp.ne.u32 p, %5, 0;\n\t"
        "tcgen05.mma.cta_group::1.kind::tf32 [%0], %1, %2, %3, {%4, %4, %4, %4}, p;\n\t}"
        :: "r"(d), "l"(ad), "l"(bd), "r"(idesc), "r"(0u), "r"(en) : "memory");
}
__device__ __forceinline__ void mma_commit(uint32_t mbar) {
    asm volatile("tcgen05.commit.cta_group::1.mbarrier::arrive::one.shared::cluster.b64 [%0];" :: "r"(mbar) : "memory");
}
// SW128 K-major smem descriptor: layout=2, version=1, SBO=64, LBO=1
__device__ __forceinline__ uint64_t mk_desc(uint32_t addr) {
    const uint64_t base = (uint64_t(2) << 61) | (uint64_t(1) << 46) | (uint64_t(64) << 32) | (uint64_t(1) << 16);
    return base | ((uint64_t)(addr >> 4) & 0x3FFF);
}

#define LDTM32(r, a) \
    asm volatile( \
        "tcgen05.ld.sync.aligned.32x32b.x32.b32 " \
        "{%0, %1, %2, %3, %4, %5, %6, %7, " \
        " %8, %9, %10, %11, %12, %13, %14, %15, " \
        " %16, %17, %18, %19, %20, %21, %22, %23, " \
        " %24, %25, %26, %27, %28, %29, %30, %31}, [%32];" \
        : "=r"((r)[0]),  "=r"((r)[1]),  "=r"((r)[2]),  "=r"((r)[3]), \
          "=r"((r)[4]),  "=r"((r)[5]),  "=r"((r)[6]),  "=r"((r)[7]), \
          "=r"((r)[8]),  "=r"((r)[9]),  "=r"((r)[10]), "=r"((r)[11]), \
          "=r"((r)[12]), "=r"((r)[13]), "=r"((r)[14]), "=r"((r)[15]), \
          "=r"((r)[16]), "=r"((r)[17]), "=r"((r)[18]), "=r"((r)[19]), \
          "=r"((r)[20]), "=r"((r)[21]), "=r"((r)[22]), "=r"((r)[23]), \
          "=r"((r)[24]), "=r"((r)[25]), "=r"((r)[26]), "=r"((r)[27]), \
          "=r"((r)[28]), "=r"((r)[29]), "=r"((r)[30]), "=r"((r)[31]) \
        : "r"(a))

// idesc: dtype=F32(1<<4), atype=TF32(2<<7), btype=TF32(2<<10), N=128(16<<17), M=128(8<<24)
#define K4_IDESC ((1u<<4) | (2u<<7) | (2u<<10) | (16u<<17) | (8u<<24))

__device__ __forceinline__ void k4_load_tile(const float* __restrict__ src, uint32_t sdst,
                                             int row0, int rowmax, int tid)
{
    // 128 rows x 128 cols f32 -> 4 K-chunks of [128 x 32] SW128-swizzled tf32
    #pragma unroll
    for (int it = 0; it < 16; it++) {
        int f = tid + it * 256;          // float4 index, 0..4095
        int r = f >> 5, q = f & 31;
        int kc = q >> 3, c4 = q & 7;
        float4 v = make_float4(0.f, 0.f, 0.f, 0.f);
        if (row0 + r < rowmax)
            v = *(const float4*)&src[(size_t)(row0 + r) * CH + q * 4];
        uint32_t off = (uint32_t)(kc * 16384 + r * 128 + c4 * 16);
        off = off ^ ((off >> 3) & 0x70);
        sts128(sdst + off, f2tf(v.x), f2tf(v.y), f2tf(v.z), f2tf(v.w));
    }
}

__device__ __forceinline__ void k4_epilogue(uint32_t dt, int m0, int n0,
                                            float* __restrict__ out, int wid, int lid)
{
    asm volatile("tcgen05.fence::after_thread_sync;" ::: "memory");
    int m = m0 + (wid & 3) * 32 + lid;
    float* row = out + (size_t)m * VSZ;   // 4B-aligned only (VSZ odd) -> scalar stores
    int cb = (wid >> 2) * 64;
    #pragma unroll
    for (int c = 0; c < 2; c++) {
        uint32_t r[32];
        LDTM32(r, dt + cb + 32 * c);
        asm volatile("tcgen05.wait::ld.sync.aligned;" ::: "memory");
        int nb = n0 + cb + 32 * c;
        if (nb + 32 <= VSZ) {
            #pragma unroll
            for (int k = 0; k < 32; k++)
                row[nb + k] = __uint_as_float(r[k]);
        } else {
            #pragma unroll
            for (int k = 0; k < 32; k++)
                if (nb + k < VSZ) row[nb + k] = __uint_as_float(r[k]);
        }
    }
}
#endif  // HAS_TCGEN05

__global__ void __launch_bounds__(256, 1) k4mma(const float* __restrict__ Wlm,
                                                float* __restrict__ out)
{
    extern __shared__ __align__(1024) char smem[];
    int tid = threadIdx.x;
    int m0 = blockIdx.x * 128;
    int g  = blockIdx.y;              // N-group 0..3, tiles jt = g, g+4, ...
    int nt = (NTILES - 1 - g) / 4 + 1;

#if HAS_TCGEN05
    __shared__ __align__(16) unsigned long long s_mbar[2];
    __shared__ uint32_t s_tmem;

    int wid = tid >> 5, lid = tid & 31;
    uint32_t sb = s2u(smem);
    uint32_t mb0 = s2u(&s_mbar[0]);
    uint32_t mb1 = s2u(&s_mbar[1]);

    if (wid == 0) {
        asm volatile("tcgen05.alloc.cta_group::1.sync.aligned.shared::cta.b32 [%0], %1;"
                     :: "r"(s2u(&s_tmem)), "r"(256u) : "memory");
        asm volatile("tcgen05.relinquish_alloc_permit.cta_group::1.sync.aligned;");
    }
    if (tid == 0) { mbar_init(mb0, 1); mbar_init(mb1, 1); }
    __syncthreads();
    uint32_t tmem;
    asm volatile("ld.shared.b32 %0, [%1];" : "=r"(tmem) : "r"(s2u(&s_tmem)));

    // A tile (Xf rows m0..m0+127), loaded once
    k4_load_tile(g_xf, sb + SMA, m0, TNUM, tid);
    uint64_t adesc = mk_desc(sb + SMA);

    int ph0 = 0, ph1 = 0;

    for (int i = 0; i < nt; i++) {
        int jt = g + 4 * i;
        int n0 = jt * 128;
        int b  = i & 1;
        uint32_t sbuf = sb + (b ? SMB1 : SMB0);

        k4_load_tile(Wlm, sbuf, n0, VSZ, tid);
        asm volatile("fence.proxy.async.shared::cta;" ::: "memory");
        __syncthreads();

        if (wid == 0 && elect1()) {
            uint64_t bdesc = mk_desc(sbuf);
            uint32_t dreg = tmem + (uint32_t)(b * 128);
            #pragma unroll
            for (int s = 0; s < 16; s++) {
                uint64_t koff = (uint64_t)((s >> 2) * 1024 + (s & 3) * 2);
                mma_tf32(dreg, adesc + koff, bdesc + koff, K4_IDESC, s > 0);
            }
            mma_commit(b ? mb1 : mb0);
        }

        if (i >= 1) {
            int pb = (i - 1) & 1;
            if (pb) { mbar_wait(mb1, ph1); ph1 ^= 1; }
            else    { mbar_wait(mb0, ph0); ph0 ^= 1; }
            k4_epilogue(tmem + pb * 128, m0, (jt - 4) * 128, out, wid, lid);
        }
        __syncthreads();
    }

    {
        int i = nt - 1;
        int pb = i & 1;
        if (pb) { mbar_wait(mb1, ph1); ph1 ^= 1; }
        else    { mbar_wait(mb0, ph0); ph0 ^= 1; }
        k4_epilogue(tmem + pb * 128, m0, (g + 4 * i) * 128, out, wid, lid);
    }

    __syncthreads();
    if (wid == 0) {
        asm volatile("tcgen05.dealloc.cta_group::1.sync.aligned.b32 %0, %1;"
                     :: "r"(tmem), "r"(256u));
    }
#else
    // -------- fallback: plain fp32 smem GEMM (baseline sm_103 target) --------
    float* sA = (float*)(smem + SMA);     // [128][128]
    float* sB = (float*)(smem + SMB0);    // [128][128]

    for (int i = tid; i < 128 * 32; i += 256) {
        int r = i >> 5, q = i & 31;
        *(float4*)&sA[r * 128 + q * 4] = *(const float4*)&g_xf[(size_t)(m0 + r) * CH + q * 4];
    }

    int tx = tid & 15, ty = tid >> 4;

    for (int t = 0; t < nt; t++) {
        int n0 = (g + 4 * t) * 128;
        __syncthreads();
        for (int i = tid; i < 128 * 32; i += 256) {
            int r = i >> 5, q = i & 31;
            float4 v = make_float4(0.f, 0.f, 0.f, 0.f);
            if (n0 + r < VSZ)
                v = *(const float4*)&Wlm[(size_t)(n0 + r) * CH + q * 4];
            *(float4*)&sB[r * 128 + q * 4] = v;
        }
        __syncthreads();

        float acc[8][8];
        #pragma unroll
        for (int i = 0; i < 8; i++)
            #pragma unroll
            for (int j = 0; j < 8; j++) acc[i][j] = 0.f;

        for (int k = 0; k < 128; k++) {
            float a[8], b[8];
            #pragma unroll
            for (int i = 0; i < 8; i++) a[i] = sA[(ty * 8 + i) * 128 + k];
            #pragma unroll
            for (int j = 0; j < 8; j++) b[j] = sB[(tx * 8 + j) * 128 + k];
            #pragma unroll
            for (int i = 0; i < 8; i++)
                #pragma unroll
                for (int j = 0; j < 8; j++) acc[i][j] += a[i] * b[j];
        }

        #pragma unroll
        for (int i = 0; i < 8; i++) {
            float* row = out + (size_t)(m0 + ty * 8 + i) * VSZ;
            #pragma unroll
            for (int j = 0; j < 8; j++) {
                int n = n0 + tx * 8 + j;
                if (n < VSZ) row[n] = acc[i][j];
            }
        }
    }
#endif
}

// ==================== launch ====================
extern "C" void kernel_launch(void* const* d_in, const int* in_sizes, int n_in,
                              void* d_out, int out_size)
{
    const int*   ids    = (const int*)  d_in[0];
    const float* emb    = (const float*)d_in[1];
    const float* router = (const float*)d_in[2];
    const float* kexp   = (const float*)d_in[3];
    const float* vexp   = (const float*)d_in[4];
    const float* skv    = (const float*)d_in[5];
    const float* svv    = (const float*)d_in[6];
    const float* kvg    = (const float*)d_in[7];
    const float* Wq     = (const float*)d_in[8];
    const float* Wo     = (const float*)d_in[9];
    const float* Wm     = (const float*)d_in[10];
    const float* bm     = (const float*)d_in[11];
    const float* g1     = (const float*)d_in[12];
    const float* b1     = (const float*)d_in[13];
    const float* g2     = (const float*)d_in[14];
    const float* b2     = (const float*)d_in[15];
    const float* Wlm    = (const float*)d_in[16];

    float* out = (float*)d_out;
    float* gate_out = out + ((size_t)out_size - (size_t)TNUM * NE);

    cudaFuncSetAttribute(k4mma, cudaFuncAttributeMaxDynamicSharedMemorySize, K4_SMEM);

    k1<<<TNUM, 128>>>(ids, emb, router, Wq, g1, b1, gate_out);
    k2<<<TNUM/TB, 256>>>(kexp, vexp, skv, svv, kvg);
    k3<<<TNUM, 128>>>(Wo, Wm, bm, g2, b2);
    dim3 g4(TNUM/128, 4);
    k4mma<<<g4, 256, K4_SMEM>>>(Wlm, out);
}

// round 5
// speedup vs baseline: 2.3170x; 2.2939x over previous
#include <cuda_runtime.h>
#include <math.h>
#include <stdint.h>

#define TNUM 4096
#define CH 128
#define NE 16
#define KB 32
#define VSZ 50257
#define NTILES 393   // ceil(50257/128)

// scratch (static device arrays — no allocation)
__device__ float g_x [TNUM*CH];
__device__ float g_q [TNUM*CH];
__device__ float g_rw[TNUM*NE];
__device__ float g_ao[TNUM*CH];
__device__ float g_xf[TNUM*CH];

// ---------------- block reduce over 128 threads ----------------
__device__ __forceinline__ float blockReduce128(float v, float* sred, int tid) {
    #pragma unroll
    for (int o = 16; o; o >>= 1) v += __shfl_down_sync(0xffffffffu, v, o);
    if ((tid & 31) == 0) sred[tid >> 5] = v;
    __syncthreads();
    return sred[0] + sred[1] + sred[2] + sred[3];
}

// ==================== K1: embed + LN1 + routing + q ====================
__global__ __launch_bounds__(128) void k1(const int* __restrict__ ids,
        const float* __restrict__ emb, const float* __restrict__ router,
        const float* __restrict__ Wq, const float* __restrict__ g1,
        const float* __restrict__ b1, float* __restrict__ gate_out)
{
    int t = blockIdx.x, tid = threadIdx.x;
    __shared__ float sx[CH];
    __shared__ float sred[4];
    __shared__ float sgl[NE];

    int id = ids[t];
    float xv = __ldg(&emb[(long long)id * CH + tid]);
    g_x[t*CH + tid] = xv;

    float mu = blockReduce128(xv, sred, tid) * (1.f/CH);
    __syncthreads();
    float d  = xv - mu;
    float var = blockReduce128(d*d, sred, tid) * (1.f/CH);
    float xln = d * rsqrtf(var + 1e-5f) * g1[tid] + b1[tid];
    sx[tid] = xln;
    __syncthreads();

    int e = tid >> 3, l = tid & 7;
    float gl = 0.f;
    #pragma unroll 4
    for (int k = l; k < CH; k += 8) gl += sx[k] * __ldg(&router[e*CH + k]);
    #pragma unroll
    for (int o = 4; o; o >>= 1) gl += __shfl_xor_sync(0xffffffffu, gl, o, 8);
    if (l == 0) sgl[e] = gl;
    __syncthreads();

    if (tid < NE) gate_out[(long long)t*NE + tid] = sgl[tid];

    float mx = -1e30f;
    #pragma unroll
    for (int i = 0; i < NE; i++) mx = fmaxf(mx, sgl[i]);
    float ss = 0.f;
    #pragma unroll
    for (int i = 0; i < NE; i++) ss += __expf(sgl[i] - mx);
    if (tid < NE) g_rw[t*NE + tid] = __expf(sgl[tid] - mx) / ss;

    float acc = 0.f;
    const float4* wr = (const float4*)(Wq + tid*CH);
    const float4* xr = (const float4*)sx;
    #pragma unroll 8
    for (int k = 0; k < 32; k++) {
        float4 w = __ldg(&wr[k]);
        float4 x4 = xr[k];
        acc += w.x*x4.x + w.y*x4.y + w.z*x4.z + w.w*x4.w;
    }
    g_q[t*CH + tid] = acc;
}

// ==================== K2: expert attention ====================
#define TB 32
#define QSTR 132
__global__ __launch_bounds__(256) void k2(const float* __restrict__ kexp,
        const float* __restrict__ vexp, const float* __restrict__ skv,
        const float* __restrict__ svv, const float* __restrict__ kvg)
{
    __shared__ float sQ[TB*QSTR];
    __shared__ float sT[KB*QSTR];
    __shared__ float sS[TB][KB+1];
    __shared__ float sRW[TB*NE];

    int t0 = blockIdx.x * TB;
    int tid = threadIdx.x;
    float g = 1.f / (1.f + __expf(-kvg[0]));

    for (int i = tid; i < TB*CH; i += 256) {
        int tt = i >> 7, cc = i & 127;
        sQ[tt*QSTR + cc] = g_q[(t0+tt)*CH + cc];
    }
    for (int i = tid; i < TB*NE; i += 256) sRW[i] = g_rw[t0*NE + i];

    int t = tid >> 3, kg = tid & 7;
    float sdyn[4] = {0,0,0,0}, sstat[4];

    for (int e = 0; e < NE; e++) {
        __syncthreads();
        for (int i = tid; i < KB*CH; i += 256) {
            int kk = i >> 7, cc = i & 127;
            sT[kk*QSTR + cc] = __ldg(&kexp[e*KB*CH + i]);
        }
        __syncthreads();
        float rwv = sRW[t*NE + e];
        float dj[4] = {0,0,0,0};
        const float4* qp = (const float4*)(sQ + t*QSTR);
        #pragma unroll 4
        for (int c4 = 0; c4 < 32; c4++) {
            float4 qv = qp[c4];
            #pragma unroll
            for (int j = 0; j < 4; j++) {
                int k = kg + 8*j;
                float4 kv = *(const float4*)(sT + k*QSTR + 4*c4);
                dj[j] += qv.x*kv.x + qv.y*kv.y + qv.z*kv.z + qv.w*kv.w;
            }
        }
        #pragma unroll
        for (int j = 0; j < 4; j++) sdyn[j] += rwv * dj[j];
    }
    __syncthreads();
    for (int i = tid; i < KB*CH; i += 256) {
        int kk = i >> 7, cc = i & 127;
        sT[kk*QSTR + cc] = __ldg(&skv[i]);
    }
    __syncthreads();
    {
        float dj[4] = {0,0,0,0};
        const float4* qp = (const float4*)(sQ + t*QSTR);
        #pragma unroll 4
        for (int c4 = 0; c4 < 32; c4++) {
            float4 qv = qp[c4];
            #pragma unroll
            for (int j = 0; j < 4; j++) {
                int k = kg + 8*j;
                float4 kv = *(const float4*)(sT + k*QSTR + 4*c4);
                dj[j] += qv.x*kv.x + qv.y*kv.y + qv.z*kv.z + qv.w*kv.w;
            }
        }
        #pragma unroll
        for (int j = 0; j < 4; j++) sstat[j] = dj[j];
    }
    const float scale = 0.08838834764831845f;
    #pragma unroll
    for (int j = 0; j < 4; j++)
        sS[t][kg + 8*j] = (g*sdyn[j] + (1.f-g)*sstat[j]) * scale;
    __syncthreads();

    if (tid < TB) {
        float mx = -1e30f;
        #pragma unroll
        for (int k = 0; k < KB; k++) mx = fmaxf(mx, sS[tid][k]);
        float ssum = 0.f;
        #pragma unroll
        for (int k = 0; k < KB; k++) { float ev = __expf(sS[tid][k] - mx); sS[tid][k] = ev; ssum += ev; }
        float inv = 1.f / ssum;
        #pragma unroll
        for (int k = 0; k < KB; k++) sS[tid][k] *= inv;
    }

    float acc[16];
    #pragma unroll
    for (int i = 0; i < 16; i++) acc[i] = 0.f;

    for (int e = 0; e < NE; e++) {
        __syncthreads();
        for (int i = tid; i < KB*CH; i += 256) {
            int kk = i >> 7, cc = i & 127;
            sT[kk*QSTR + cc] = __ldg(&vexp[e*KB*CH + i]);
        }
        __syncthreads();
        float we = g * sRW[t*NE + e];
        #pragma unroll 4
        for (int k = 0; k < KB; k++) {
            float w = we * sS[t][k];
            #pragma unroll
            for (int j = 0; j < 4; j++) {
                float4 vv = *(const float4*)(sT + k*QSTR + 4*(kg + 8*j));
                acc[j*4+0] += w*vv.x; acc[j*4+1] += w*vv.y;
                acc[j*4+2] += w*vv.z; acc[j*4+3] += w*vv.w;
            }
        }
    }
    __syncthreads();
    for (int i = tid; i < KB*CH; i += 256) {
        int kk = i >> 7, cc = i & 127;
        sT[kk*QSTR + cc] = __ldg(&svv[i]);
    }
    __syncthreads();
    {
        float we = 1.f - g;
        #pragma unroll 4
        for (int k = 0; k < KB; k++) {
            float w = we * sS[t][k];
            #pragma unroll
            for (int j = 0; j < 4; j++) {
                float4 vv = *(const float4*)(sT + k*QSTR + 4*(kg + 8*j));
                acc[j*4+0] += w*vv.x; acc[j*4+1] += w*vv.y;
                acc[j*4+2] += w*vv.z; acc[j*4+3] += w*vv.w;
            }
        }
    }
    #pragma unroll
    for (int j = 0; j < 4; j++) {
        float4 o;
        o.x = acc[j*4+0]; o.y = acc[j*4+1]; o.z = acc[j*4+2]; o.w = acc[j*4+3];
        *(float4*)&g_ao[(t0+t)*CH + 4*(kg + 8*j)] = o;
    }
}

// ==================== K3: Wo + residual + LN2 + MLP + residual ====================
__global__ __launch_bounds__(128) void k3(const float* __restrict__ Wo,
        const float* __restrict__ Wm, const float* __restrict__ bm,
        const float* __restrict__ g2, const float* __restrict__ b2)
{
    int t = blockIdx.x, tid = threadIdx.x;
    __shared__ float sa[CH];
    __shared__ float sred[4];

    sa[tid] = g_ao[t*CH + tid];
    __syncthreads();

    float o = 0.f;
    {
        const float4* wr = (const float4*)(Wo + tid*CH);
        const float4* ar = (const float4*)sa;
        #pragma unroll 8
        for (int k = 0; k < 32; k++) {
            float4 w = __ldg(&wr[k]);
            float4 a4 = ar[k];
            o += w.x*a4.x + w.y*a4.y + w.z*a4.z + w.w*a4.w;
        }
    }
    float x2 = g_x[t*CH + tid] + o;

    __syncthreads();
    float mu = blockReduce128(x2, sred, tid) * (1.f/CH);
    __syncthreads();
    float d = x2 - mu;
    float var = blockReduce128(d*d, sred, tid) * (1.f/CH);
    float xln = d * rsqrtf(var + 1e-5f) * g2[tid] + b2[tid];
    __syncthreads();
    sa[tid] = xln;
    __syncthreads();

    float m = __ldg(&bm[tid]);
    {
        const float4* wr = (const float4*)(Wm + tid*CH);
        const float4* ar = (const float4*)sa;
        #pragma unroll 8
        for (int k = 0; k < 32; k++) {
            float4 w = __ldg(&wr[k]);
            float4 a4 = ar[k];
            m += w.x*a4.x + w.y*a4.y + w.z*a4.z + w.w*a4.w;
        }
    }
    g_xf[t*CH + tid] = x2 + m;
}

// ==================== K4: LM head GEMM ====================
// D[4096,50257] = Xf[4096,128] @ Wlm[50257,128]^T  (both K-major)

// Feature gate: tcgen05 only exists on the arch-specific (103a) target.
#if defined(__CUDA_ARCH__) && (__CUDA_ARCH__ == 1030) && defined(__CUDA_ARCH_FEAT_SM103_ALL)
#define HAS_TCGEN05 1
#else
#define HAS_TCGEN05 0
#endif

__device__ __forceinline__ uint32_t s2u(const void* p) {
    uint32_t a;
    asm("{ .reg .u64 t; cvta.to.shared.u64 t, %1; cvt.u32.u64 %0, t; }" : "=r"(a) : "l"(p));
    return a;
}

#define SMA 0
#define SMB0 65536
#define SMB1 131072
#define K4_SMEM 196608

#if HAS_TCGEN05

__device__ __forceinline__ uint32_t f2tf(float f) {
    uint32_t r; asm("cvt.rna.tf32.f32 %0, %1;" : "=r"(r) : "f"(f)); return r;
}
__device__ __forceinline__ bool elect1() {
    uint32_t p;
    asm volatile("{ .reg .pred p; elect.sync _|p, 0xFFFFFFFF; selp.b32 %0, 1, 0, p; }" : "=r"(p));
    return p != 0;
}
__device__ __forceinline__ void mbar_init(uint32_t a, uint32_t cnt) {
    asm volatile("mbarrier.init.shared.b64 [%0], %1;" :: "r"(a), "r"(cnt) : "memory");
}
__device__ __forceinline__ void mbar_wait(uint32_t a, uint32_t ph) {
    asm volatile(
        "{\n\t.reg .pred P;\n"
        "W_%=:\n\t"
        "mbarrier.try_wait.parity.acquire.cta.shared::cta.b64 P, [%0], %1, 0x989680;\n\t"
        "@P bra D_%=;\n\t"
        "bra W_%=;\n"
        "D_%=:\n\t}"
        :: "r"(a), "r"(ph) : "memory");
}
__device__ __forceinline__ void sts128(uint32_t a, uint32_t r0, uint32_t r1, uint32_t r2, uint32_t r3) {
    asm volatile("st.shared.v4.b32 [%0], {%1, %2, %3, %4};" :: "r"(a), "r"(r0), "r"(r1), "r"(r2), "r"(r3) : "memory");
}
__device__ __forceinline__ void mma_tf32(uint32_t d, uint64_t ad, uint64_t bd, uint32_t idesc, bool accum) {
    uint32_t en = accum ? 1u : 0u;
    asm volatile(
        "{\n\t.reg .pred p;\n\t"
        "setp.ne.u32 p, %5, 0;\n\t"
        "tcgen05.mma.cta_group::1.kind::tf32 [%0], %1, %2, %3, {%4, %4, %4, %4}, p;\n\t}"
        :: "r"(d), "l"(ad), "l"(bd), "r"(idesc), "r"(0u), "r"(en) : "memory");
}
__device__ __forceinline__ void mma_commit(uint32_t mbar) {
    asm volatile("tcgen05.commit.cta_group::1.mbarrier::arrive::one.shared::cluster.b64 [%0];" :: "r"(mbar) : "memory");
}
// SW128 K-major smem descriptor: layout=2, version=1, SBO=64, LBO=1
__device__ __forceinline__ uint64_t mk_desc(uint32_t addr) {
    const uint64_t base = (uint64_t(2) << 61) | (uint64_t(1) << 46) | (uint64_t(64) << 32) | (uint64_t(1) << 16);
    return base | ((uint64_t)(addr >> 4) & 0x3FFF);
}

#define LDTM32(r, a) \
    asm volatile( \
        "tcgen05.ld.sync.aligned.32x32b.x32.b32 " \
        "{%0, %1, %2, %3, %4, %5, %6, %7, " \
        " %8, %9, %10, %11, %12, %13, %14, %15, " \
        " %16, %17, %18, %19, %20, %21, %22, %23, " \
        " %24, %25, %26, %27, %28, %29, %30, %31}, [%32];" \
        : "=r"((r)[0]),  "=r"((r)[1]),  "=r"((r)[2]),  "=r"((r)[3]), \
          "=r"((r)[4]),  "=r"((r)[5]),  "=r"((r)[6]),  "=r"((r)[7]), \
          "=r"((r)[8]),  "=r"((r)[9]),  "=r"((r)[10]), "=r"((r)[11]), \
          "=r"((r)[12]), "=r"((r)[13]), "=r"((r)[14]), "=r"((r)[15]), \
          "=r"((r)[16]), "=r"((r)[17]), "=r"((r)[18]), "=r"((r)[19]), \
          "=r"((r)[20]), "=r"((r)[21]), "=r"((r)[22]), "=r"((r)[23]), \
          "=r"((r)[24]), "=r"((r)[25]), "=r"((r)[26]), "=r"((r)[27]), \
          "=r"((r)[28]), "=r"((r)[29]), "=r"((r)[30]), "=r"((r)[31]) \
        : "r"(a))

// idesc: dtype=F32(1<<4), atype=TF32(2<<7), btype=TF32(2<<10), N=128(16<<17), M=128(8<<24)
#define K4_IDESC ((1u<<4) | (2u<<7) | (2u<<10) | (16u<<17) | (8u<<24))

__device__ __forceinline__ void k4_load_tile(const float* __restrict__ src, uint32_t sdst,
                                             int row0, int rowmax, int tid)
{
    // 128 rows x 128 cols f32 -> 4 K-chunks of [128 x 32] SW128-swizzled tf32
    #pragma unroll
    for (int it = 0; it < 16; it++) {
        int f = tid + it * 256;          // float4 index, 0..4095
        int r = f >> 5, q = f & 31;
        int kc = q >> 3, c4 = q & 7;
        float4 v = make_float4(0.f, 0.f, 0.f, 0.f);
        if (row0 + r < rowmax)
            v = *(const float4*)&src[(size_t)(row0 + r) * CH + q * 4];
        uint32_t off = (uint32_t)(kc * 16384 + r * 128 + c4 * 16);
        off = off ^ ((off >> 3) & 0x70);
        sts128(sdst + off, f2tf(v.x), f2tf(v.y), f2tf(v.z), f2tf(v.w));
    }
}

// Epilogue v2: LDTM -> swizzled SMEM transpose (reusing the retired B buffer)
// -> coalesced row-major scalar stores (1-2 lines per STG instead of 32).
__device__ __forceinline__ void k4_epilogue(uint32_t dt, float* __restrict__ scratch,
                                            int m0, int n0,
                                            float* __restrict__ out, int tid)
{
    asm volatile("tcgen05.fence::after_thread_sync;" ::: "memory");
    int wid = tid >> 5, lid = tid & 31;
    int row = (wid & 3) * 32 + lid;     // TMEM lane -> D row
    int cb  = (wid >> 2) * 64;          // warp-pair column half
    #pragma unroll
    for (int c = 0; c < 2; c++) {
        uint32_t r[32];
        LDTM32(r, dt + cb + 32 * c);
        asm volatile("tcgen05.wait::ld.sync.aligned;" ::: "memory");
        #pragma unroll
        for (int k = 0; k < 32; k++) {
            int col = cb + 32 * c + k;
            scratch[row * 128 + (col ^ lid)] = __uint_as_float(r[k]);
        }
    }
    __syncthreads();

    if (n0 + 128 <= VSZ) {
        #pragma unroll
        for (int rr = 0; rr < 16; rr++) {
            int r2 = wid * 16 + rr;
            float* orow = out + (size_t)(m0 + r2) * VSZ + n0;
            int sw = r2 & 31;
            #pragma unroll
            for (int j = 0; j < 4; j++) {
                int col = lid + 32 * j;
                orow[col] = scratch[r2 * 128 + (col ^ sw)];
            }
        }
    } else {
        for (int rr = 0; rr < 16; rr++) {
            int r2 = wid * 16 + rr;
            float* orow = out + (size_t)(m0 + r2) * VSZ;
            int sw = r2 & 31;
            #pragma unroll
            for (int j = 0; j < 4; j++) {
                int col = lid + 32 * j;
                if (n0 + col < VSZ) orow[n0 + col] = scratch[r2 * 128 + (col ^ sw)];
            }
        }
    }
}
#endif  // HAS_TCGEN05

__global__ void __launch_bounds__(256, 1) k4mma(const float* __restrict__ Wlm,
                                                float* __restrict__ out)
{
    extern __shared__ __align__(1024) char smem[];
    int tid = threadIdx.x;
    int m0 = blockIdx.x * 128;
    int g  = blockIdx.y;              // N-group 0..3, tiles jt = g, g+4, ...
    int nt = (NTILES - 1 - g) / 4 + 1;

#if HAS_TCGEN05
    __shared__ __align__(16) unsigned long long s_mbar[2];
    __shared__ uint32_t s_tmem;

    int wid = tid >> 5;
    uint32_t sb = s2u(smem);
    uint32_t mb0 = s2u(&s_mbar[0]);
    uint32_t mb1 = s2u(&s_mbar[1]);

    if (wid == 0) {
        asm volatile("tcgen05.alloc.cta_group::1.sync.aligned.shared::cta.b32 [%0], %1;"
                     :: "r"(s2u(&s_tmem)), "r"(256u) : "memory");
        asm volatile("tcgen05.relinquish_alloc_permit.cta_group::1.sync.aligned;");
    }
    if (tid == 0) { mbar_init(mb0, 1); mbar_init(mb1, 1); }
    __syncthreads();
    uint32_t tmem;
    asm volatile("ld.shared.b32 %0, [%1];" : "=r"(tmem) : "r"(s2u(&s_tmem)));

    // A tile (Xf rows m0..m0+127), loaded once
    k4_load_tile(g_xf, sb + SMA, m0, TNUM, tid);
    uint64_t adesc = mk_desc(sb + SMA);

    int ph0 = 0, ph1 = 0;

    for (int i = 0; i < nt; i++) {
        int jt = g + 4 * i;
        int n0 = jt * 128;
        int b  = i & 1;
        uint32_t sbuf = sb + (b ? SMB1 : SMB0);

        k4_load_tile(Wlm, sbuf, n0, VSZ, tid);
        asm volatile("fence.proxy.async.shared::cta;" ::: "memory");
        __syncthreads();

        if (wid == 0 && elect1()) {
            uint64_t bdesc = mk_desc(sbuf);
            uint32_t dreg = tmem + (uint32_t)(b * 128);
            #pragma unroll
            for (int s = 0; s < 16; s++) {
                uint64_t koff = (uint64_t)((s >> 2) * 1024 + (s & 3) * 2);
                mma_tf32(dreg, adesc + koff, bdesc + koff, K4_IDESC, s > 0);
            }
            mma_commit(b ? mb1 : mb0);
        }

        // epilogue of previous tile overlaps current MMA; its retired B buffer
        // (pb) is the transpose scratch — MMA(i-1) finished reading it (mbar).
        if (i >= 1) {
            int pb = (i - 1) & 1;
            if (pb) { mbar_wait(mb1, ph1); ph1 ^= 1; }
            else    { mbar_wait(mb0, ph0); ph0 ^= 1; }
            k4_epilogue(tmem + pb * 128,
                        (float*)(smem + (pb ? SMB1 : SMB0)),
                        m0, (jt - 4) * 128, out, tid);
        }
        __syncthreads();
    }

    {
        int i = nt - 1;
        int pb = i & 1;
        if (pb) { mbar_wait(mb1, ph1); ph1 ^= 1; }
        else    { mbar_wait(mb0, ph0); ph0 ^= 1; }
        k4_epilogue(tmem + pb * 128,
                    (float*)(smem + (pb ? SMB1 : SMB0)),
                    m0, (g + 4 * i) * 128, out, tid);
    }

    __syncthreads();
    if (wid == 0) {
        asm volatile("tcgen05.dealloc.cta_group::1.sync.aligned.b32 %0, %1;"
                     :: "r"(tmem), "r"(256u));
    }
#else
    // -------- fallback: plain fp32 smem GEMM (baseline sm_103 target) --------
    float* sA = (float*)(smem + SMA);     // [128][128]
    float* sB = (float*)(smem + SMB0);    // [128][128]

    for (int i = tid; i < 128 * 32; i += 256) {
        int r = i >> 5, q = i & 31;
        *(float4*)&sA[r * 128 + q * 4] = *(const float4*)&g_xf[(size_t)(m0 + r) * CH + q * 4];
    }

    int tx = tid & 15, ty = tid >> 4;

    for (int t = 0; t < nt; t++) {
        int n0 = (g + 4 * t) * 128;
        __syncthreads();
        for (int i = tid; i < 128 * 32; i += 256) {
            int r = i >> 5, q = i & 31;
            float4 v = make_float4(0.f, 0.f, 0.f, 0.f);
            if (n0 + r < VSZ)
                v = *(const float4*)&Wlm[(size_t)(n0 + r) * CH + q * 4];
            *(float4*)&sB[r * 128 + q * 4] = v;
        }
        __syncthreads();

        float acc[8][8];
        #pragma unroll
        for (int i = 0; i < 8; i++)
            #pragma unroll
            for (int j = 0; j < 8; j++) acc[i][j] = 0.f;

        for (int k = 0; k < 128; k++) {
            float a[8], b[8];
            #pragma unroll
            for (int i = 0; i < 8; i++) a[i] = sA[(ty * 8 + i) * 128 + k];
            #pragma unroll
            for (int j = 0; j < 8; j++) b[j] = sB[(tx * 8 + j) * 128 + k];
            #pragma unroll
            for (int i = 0; i < 8; i++)
                #pragma unroll
                for (int j = 0; j < 8; j++) acc[i][j] += a[i] * b[j];
        }

        #pragma unroll
        for (int i = 0; i < 8; i++) {
            float* row = out + (size_t)(m0 + ty * 8 + i) * VSZ;
            #pragma unroll
            for (int j = 0; j < 8; j++) {
                int n = n0 + tx * 8 + j;
                if (n < VSZ) row[n] = acc[i][j];
            }
        }
    }
#endif
}

// ==================== launch ====================
extern "C" void kernel_launch(void* const* d_in, const int* in_sizes, int n_in,
                              void* d_out, int out_size)
{
    const int*   ids    = (const int*)  d_in[0];
    const float* emb    = (const float*)d_in[1];
    const float* router = (const float*)d_in[2];
    const float* kexp   = (const float*)d_in[3];
    const float* vexp   = (const float*)d_in[4];
    const float* skv    = (const float*)d_in[5];
    const float* svv    = (const float*)d_in[6];
    const float* kvg    = (const float*)d_in[7];
    const float* Wq     = (const float*)d_in[8];
    const float* Wo     = (const float*)d_in[9];
    const float* Wm     = (const float*)d_in[10];
    const float* bm     = (const float*)d_in[11];
    const float* g1     = (const float*)d_in[12];
    const float* b1     = (const float*)d_in[13];
    const float* g2     = (const float*)d_in[14];
    const float* b2     = (const float*)d_in[15];
    const float* Wlm    = (const float*)d_in[16];

    float* out = (float*)d_out;
    float* gate_out = out + ((size_t)out_size - (size_t)TNUM * NE);

    cudaFuncSetAttribute(k4mma, cudaFuncAttributeMaxDynamicSharedMemorySize, K4_SMEM);

    k1<<<TNUM, 128>>>(ids, emb, router, Wq, g1, b1, gate_out);
    k2<<<TNUM/TB, 256>>>(kexp, vexp, skv, svv, kvg);
    k3<<<TNUM, 128>>>(Wo, Wm, bm, g2, b2);
    dim3 g4(TNUM/128, 4);
    k4mma<<<g4, 256, K4_SMEM>>>(Wlm, out);
}